// round 2
// baseline (speedup 1.0000x reference)
#include <cuda_runtime.h>

// LSTMModel: 2-layer LSTM (B=2048, T=1000, I=13, H=32) + Linear(32)->ReLU->Linear(3)
// Fused persistent kernel. Grid=128 blocks x 128 threads (4 warps).
// Each warp owns R=4 batch elements for the entire sequence; lane j owns gate
// rows {j, 32+j, 64+j, 96+j}. Weights permuted in SMEM so the 4 gate weights
// for a given k are one float4 (single conflict-free LDS.128), reused across
// the 4 batches. h vectors exchanged via per-warp SMEM broadcast reads.

#define BB    2048
#define TT    1000
#define II    13
#define HH    32
#define NG    128      // 4*H gate rows
#define NC    3
#define WARPS 4
#define RB    4        // batches per warp
#define BPB   (WARPS * RB)   // 16 batches per block
#define GRIDN (BB / BPB)     // 128 blocks

struct Smem {
    float Wx0[16 * NG];      // [k(0..15, padded from 13)][j*4+q]
    float Wh0[HH * NG];      // [k][j*4+q]
    float Wx1[HH * NG];
    float Wh1[HH * NG];
    float bias0[NG];         // bih0+bhh0 permuted to j*4+q
    float bias1[NG];
    float Wc1t[HH * HH];     // [k][j]
    float Wc2s[4 * HH];      // [c][k] (row-padded to 4)
    float bc1s[HH];
    float bc2s[4];
    // state region (must stay contiguous for the zero-init loop)
    float h0s[WARPS][RB][HH];
    float h1s[WARPS][RB][HH];
    float xs [WARPS][RB][16]; // x_t staged, padded 13->16 with zeros
};

__device__ __forceinline__ float sigf(float v) {
    float e = __expf(-v);
    return __fdividef(1.0f, 1.0f + e);
}
__device__ __forceinline__ float tanh_f(float v) {
    v = fminf(12.0f, fmaxf(-12.0f, v));
    float e = __expf(-2.0f * v);
    return __fdividef(1.0f - e, 1.0f + e);
}

// acc[r][g] += sum_k vec[r][k] * W[k][j*4+g], over NKG groups of 4 k's.
template <int NKG, int VS>
__device__ __forceinline__ void mm(const float* __restrict__ W,
                                   const float* __restrict__ vb,
                                   int j, float acc[RB][4]) {
#pragma unroll
    for (int kg = 0; kg < NKG; kg++) {
        float4 w0 = reinterpret_cast<const float4*>(W + (kg * 4 + 0) * NG)[j];
        float4 w1 = reinterpret_cast<const float4*>(W + (kg * 4 + 1) * NG)[j];
        float4 w2 = reinterpret_cast<const float4*>(W + (kg * 4 + 2) * NG)[j];
        float4 w3 = reinterpret_cast<const float4*>(W + (kg * 4 + 3) * NG)[j];
#pragma unroll
        for (int r = 0; r < RB; r++) {
            float4 v = *reinterpret_cast<const float4*>(vb + r * VS + kg * 4);
            float a0 = acc[r][0], a1 = acc[r][1], a2 = acc[r][2], a3 = acc[r][3];
            a0 = fmaf(v.x, w0.x, a0); a1 = fmaf(v.x, w0.y, a1);
            a2 = fmaf(v.x, w0.z, a2); a3 = fmaf(v.x, w0.w, a3);
            a0 = fmaf(v.y, w1.x, a0); a1 = fmaf(v.y, w1.y, a1);
            a2 = fmaf(v.y, w1.z, a2); a3 = fmaf(v.y, w1.w, a3);
            a0 = fmaf(v.z, w2.x, a0); a1 = fmaf(v.z, w2.y, a1);
            a2 = fmaf(v.z, w2.z, a2); a3 = fmaf(v.z, w2.w, a3);
            a0 = fmaf(v.w, w3.x, a0); a1 = fmaf(v.w, w3.y, a1);
            a2 = fmaf(v.w, w3.z, a2); a3 = fmaf(v.w, w3.w, a3);
            acc[r][0] = a0; acc[r][1] = a1; acc[r][2] = a2; acc[r][3] = a3;
        }
    }
}

__global__ void __launch_bounds__(WARPS * 32, 1)
lstm_fused_kernel(const float* __restrict__ x,
                  const float* __restrict__ Wih0, const float* __restrict__ Whh0,
                  const float* __restrict__ bih0, const float* __restrict__ bhh0,
                  const float* __restrict__ Wih1, const float* __restrict__ Whh1,
                  const float* __restrict__ bih1, const float* __restrict__ bhh1,
                  const float* __restrict__ Wc1,  const float* __restrict__ bc1,
                  const float* __restrict__ Wc2,  const float* __restrict__ bc2,
                  float* __restrict__ out) {
    extern __shared__ char smem_raw[];
    Smem& s = *reinterpret_cast<Smem*>(smem_raw);
    const int tid = threadIdx.x;

    // ---- cooperative weight permute into SMEM ----
    for (int i = tid; i < 16 * NG; i += WARPS * 32) {
        int k = i >> 7, c = i & 127, jj = c >> 2, q = c & 3;
        s.Wx0[i] = (k < II) ? Wih0[(q * HH + jj) * II + k] : 0.0f;
    }
    for (int i = tid; i < HH * NG; i += WARPS * 32) {
        int k = i >> 7, c = i & 127, jj = c >> 2, q = c & 3;
        int row = q * HH + jj;
        s.Wh0[i] = Whh0[row * HH + k];
        s.Wx1[i] = Wih1[row * HH + k];
        s.Wh1[i] = Whh1[row * HH + k];
    }
    for (int i = tid; i < NG; i += WARPS * 32) {
        int jj = i >> 2, q = i & 3;
        int row = q * HH + jj;
        s.bias0[i] = bih0[row] + bhh0[row];
        s.bias1[i] = bih1[row] + bhh1[row];
    }
    for (int i = tid; i < HH * HH; i += WARPS * 32) {
        int k = i >> 5, jj = i & 31;
        s.Wc1t[i] = Wc1[jj * HH + k];
    }
    for (int i = tid; i < NC * HH; i += WARPS * 32) s.Wc2s[i] = Wc2[i];
    if (tid < HH) s.bc1s[tid] = bc1[tid];
    if (tid < NC) s.bc2s[tid] = bc2[tid];
    // zero the contiguous state region (h0s, h1s, xs incl. padding)
    {
        float* zp = &s.h0s[0][0][0];
        const int zn = WARPS * RB * HH * 2 + WARPS * RB * 16;
        for (int i = tid; i < zn; i += WARPS * 32) zp[i] = 0.0f;
    }
    __syncthreads();

    const int w = tid >> 5;
    const int j = tid & 31;
    const int b0 = blockIdx.x * BPB + w * RB;

    const float* xp0 = x + (size_t)b0 * (TT * II) + j;
    const float4 bv0 = reinterpret_cast<const float4*>(s.bias0)[j];
    const float4 bv1 = reinterpret_cast<const float4*>(s.bias1)[j];
    const float* xsv = &s.xs[w][0][0];
    const float* h0v = &s.h0s[w][0][0];
    const float* h1v = &s.h1s[w][0][0];

    float c0[RB] = {0.f, 0.f, 0.f, 0.f};
    float c1[RB] = {0.f, 0.f, 0.f, 0.f};
    float xv[RB];
    const bool xl = (j < II);
    if (xl) {
#pragma unroll
        for (int r = 0; r < RB; r++) xv[r] = xp0[(size_t)r * (TT * II)];
    }

    for (int t = 0; t < TT; t++) {
        // commit prefetched x_t to SMEM
        if (xl) {
#pragma unroll
            for (int r = 0; r < RB; r++) s.xs[w][r][j] = xv[r];
        }
        __syncwarp();   // also orders last step's h1s write before its reads
        // prefetch x_{t+1} (latency hidden behind this step's compute)
        if (xl && (t + 1 < TT)) {
#pragma unroll
            for (int r = 0; r < RB; r++)
                xv[r] = xp0[(size_t)r * (TT * II) + (size_t)(t + 1) * II];
        }

        float acc[RB][4];
        float hn[RB];

        // ---- layer 0 ----
#pragma unroll
        for (int r = 0; r < RB; r++) {
            acc[r][0] = bv0.x; acc[r][1] = bv0.y; acc[r][2] = bv0.z; acc[r][3] = bv0.w;
        }
        mm<4, 16>(s.Wx0, xsv, j, acc);   // input contribution (13 padded to 16)
        mm<8, HH>(s.Wh0, h0v, j, acc);   // recurrent
#pragma unroll
        for (int r = 0; r < RB; r++) {
            float ig = sigf(acc[r][0]);
            float fg = sigf(acc[r][1]);
            float gg = tanh_f(acc[r][2]);
            float og = sigf(acc[r][3]);
            c0[r] = fmaf(fg, c0[r], ig * gg);
            hn[r] = og * tanh_f(c0[r]);
        }
        __syncwarp();                      // all lanes done reading old h0
#pragma unroll
        for (int r = 0; r < RB; r++) s.h0s[w][r][j] = hn[r];
        __syncwarp();                      // new h0 visible

        // ---- layer 1 ----
#pragma unroll
        for (int r = 0; r < RB; r++) {
            acc[r][0] = bv1.x; acc[r][1] = bv1.y; acc[r][2] = bv1.z; acc[r][3] = bv1.w;
        }
        mm<8, HH>(s.Wx1, h0v, j, acc);   // input = new h0
        mm<8, HH>(s.Wh1, h1v, j, acc);   // recurrent (old h1)
#pragma unroll
        for (int r = 0; r < RB; r++) {
            float ig = sigf(acc[r][0]);
            float fg = sigf(acc[r][1]);
            float gg = tanh_f(acc[r][2]);
            float og = sigf(acc[r][3]);
            c1[r] = fmaf(fg, c1[r], ig * gg);
            hn[r] = og * tanh_f(c1[r]);
        }
        __syncwarp();                      // all lanes done reading old h1
#pragma unroll
        for (int r = 0; r < RB; r++) s.h1s[w][r][j] = hn[r];
        // next iteration's first __syncwarp orders this write
    }
    __syncwarp();

    // ---- classifier head: hidden = relu(h_T @ Wc1^T + bc1); out = hidden @ Wc2^T + bc2
#pragma unroll
    for (int r = 0; r < RB; r++) {
        float hv = s.bc1s[j];
#pragma unroll
        for (int k = 0; k < HH; k++)
            hv = fmaf(s.h1s[w][r][k], s.Wc1t[k * HH + j], hv);
        s.h0s[w][r][j] = fmaxf(hv, 0.0f);   // reuse h0s as scratch
    }
    __syncwarp();
    if (j < NC) {
#pragma unroll
        for (int r = 0; r < RB; r++) {
            float o = s.bc2s[j];
#pragma unroll
            for (int k = 0; k < HH; k++)
                o = fmaf(s.h0s[w][r][k], s.Wc2s[j * HH + k], o);
            out[(size_t)(b0 + r) * NC + j] = o;
        }
    }
}

extern "C" void kernel_launch(void* const* d_in, const int* in_sizes, int n_in,
                              void* d_out, int out_size) {
    const float* x    = (const float*)d_in[0];
    const float* Wih0 = (const float*)d_in[1];
    const float* Whh0 = (const float*)d_in[2];
    const float* bih0 = (const float*)d_in[3];
    const float* bhh0 = (const float*)d_in[4];
    const float* Wih1 = (const float*)d_in[5];
    const float* Whh1 = (const float*)d_in[6];
    const float* bih1 = (const float*)d_in[7];
    const float* bhh1 = (const float*)d_in[8];
    const float* Wc1  = (const float*)d_in[9];
    const float* bc1  = (const float*)d_in[10];
    const float* Wc2  = (const float*)d_in[11];
    const float* bc2  = (const float*)d_in[12];
    float* out = (float*)d_out;

    cudaFuncSetAttribute(lstm_fused_kernel,
                         cudaFuncAttributeMaxDynamicSharedMemorySize,
                         (int)sizeof(Smem));

    lstm_fused_kernel<<<GRIDN, WARPS * 32, sizeof(Smem)>>>(
        x, Wih0, Whh0, bih0, bhh0, Wih1, Whh1, bih1, bhh1,
        Wc1, bc1, Wc2, bc2, out);
}

// round 3
// speedup vs baseline: 1.4130x; 1.4130x over previous
#include <cuda_runtime.h>

// 2-layer LSTM (B=2048, T=1000, I=13, H=32) + Linear(32)->ReLU->Linear(3).
// Persistent fused kernel, 128 blocks x 256 threads.
// Block = 16 batches, split into two independent 8-batch halves (warps 0-3 / 4-7)
// synchronized by named barriers (ids 1,2) so the halves interleave phases.
// Within a half: thread lt (0..127) owns gate row lt; its 109 weights are
// REGISTER-RESIDENT, pre-packed as f32x2 pairs over k. GEMM uses fma.rn.f32x2
// (2 MACs/instr): acc lanes = even/odd-k partial sums, folded by one lane-add.
// All shared-memory GEMM reads are warp-broadcast float4 (conflict-free).

#define BB    2048
#define TT    1000
#define II    13
#define HH    32
#define NC    3
#define NB    8            // batches per half
#define GSTR  9            // gate smem row stride (coprime with 32 banks)

typedef unsigned long long ull;

struct alignas(16) Smem {
    float xs[2][NB][16];        // x_t staged, k padded 13->16 (zeros)
    float h0[2][NB][HH];
    float h1[2][NB][HH];
    float gates[2][128 * GSTR]; // [gate_row][batch], stride 9
};

__device__ __forceinline__ ull ffma2(ull a, ull b, ull c) {
    ull d;
    asm("fma.rn.f32x2 %0, %1, %2, %3;" : "=l"(d) : "l"(a), "l"(b), "l"(c));
    return d;
}
__device__ __forceinline__ ull packf2(float lo, float hi) {
    ull r;
    asm("mov.b64 %0, {%1, %2};" : "=l"(r) : "f"(lo), "f"(hi));
    return r;
}
__device__ __forceinline__ float hadd2(ull a) {
    float lo, hi;
    asm("mov.b64 {%0, %1}, %2;" : "=f"(lo), "=f"(hi) : "l"(a));
    return lo + hi;
}
__device__ __forceinline__ ull d2l(double d) { return __double_as_longlong(d); }

__device__ __forceinline__ float sigf(float v) {
    float e = __expf(-v);
    return __fdividef(1.0f, 1.0f + e);
}
__device__ __forceinline__ float tanh_f(float v) {
    v = fminf(12.0f, fmaxf(-12.0f, v));
    float e = __expf(-2.0f * v);
    return __fdividef(1.0f - e, 1.0f + e);
}

// acc[b] += sum over NC4 float4-chunks of v-pairs * w-pairs (f32x2)
template <int NC4, int NW, int BSTR>
__device__ __forceinline__ void gemm_part(ull (&acc)[NB], const float* vbase,
                                          const ull (&w)[NW]) {
#pragma unroll
    for (int c = 0; c < NC4; c++) {
#pragma unroll
        for (int b = 0; b < NB; b++) {
            double2 v = *reinterpret_cast<const double2*>(vbase + b * BSTR + c * 4);
            acc[b] = ffma2(d2l(v.x), w[2 * c + 0], acc[b]);
            acc[b] = ffma2(d2l(v.y), w[2 * c + 1], acc[b]);
        }
    }
}

__global__ void __launch_bounds__(256, 1)
lstm_fused_kernel(const float* __restrict__ x,
                  const float* __restrict__ Wih0, const float* __restrict__ Whh0,
                  const float* __restrict__ bih0, const float* __restrict__ bhh0,
                  const float* __restrict__ Wih1, const float* __restrict__ Whh1,
                  const float* __restrict__ bih1, const float* __restrict__ bhh1,
                  const float* __restrict__ Wc1,  const float* __restrict__ bc1,
                  const float* __restrict__ Wc2,  const float* __restrict__ bc2,
                  float* __restrict__ out) {
    __shared__ Smem s;
    const int tid  = threadIdx.x;
    const int half = tid >> 7;          // 0 or 1
    const int lt   = tid & 127;         // local thread = gate row
    const int bbase = blockIdx.x * 16 + half * NB;

    // ---- zero state region (xs, h0, h1 are contiguous at struct start) ----
    {
        float* zp = &s.xs[0][0][0];
        const int zn = (int)((sizeof(s.xs) + sizeof(s.h0) + sizeof(s.h1)) / 4);
        for (int i = tid; i < zn; i += 256) zp[i] = 0.0f;
    }

    // ---- register-resident weights, pre-packed as k-pairs ----
    const int row = lt;
    ull wx0[8], wh0[16], wx1[16], wh1[16];
#pragma unroll
    for (int p = 0; p < 8; p++) {
        float lo = (2 * p     < II) ? Wih0[row * II + 2 * p]     : 0.0f;
        float hi = (2 * p + 1 < II) ? Wih0[row * II + 2 * p + 1] : 0.0f;
        wx0[p] = packf2(lo, hi);
    }
#pragma unroll
    for (int p = 0; p < 16; p++) {
        wh0[p] = packf2(Whh0[row * HH + 2 * p], Whh0[row * HH + 2 * p + 1]);
        wx1[p] = packf2(Wih1[row * HH + 2 * p], Wih1[row * HH + 2 * p + 1]);
        wh1[p] = packf2(Whh1[row * HH + 2 * p], Whh1[row * HH + 2 * p + 1]);
    }
    const ull b0p = packf2(bih0[row] + bhh0[row], 0.0f);
    const ull b1p = packf2(bih1[row] + bhh1[row], 0.0f);

    // ---- x staging map: thread -> (batch sb, k sk) ----
    const int sb = lt >> 4, sk = lt & 15;
    const bool xload = (sk < II);
    const float* xptr = x + (size_t)(bbase + sb) * TT * II + sk;
    float xv = xload ? xptr[0] : 0.0f;

    // ---- elementwise map: thread -> (unit eu, batches eb, eb+4) ----
    const int eu = lt & 31;
    const int eb = lt >> 5;
    float c0[2] = {0.f, 0.f}, c1[2] = {0.f, 0.f};

    float* gs = s.gates[half];
    const float* h0v = &s.h0[half][0][0];
    const float* h1v = &s.h1[half][0][0];
    const float* xsv = &s.xs[half][0][0];
    const int barid = half + 1;

    __syncthreads();

#define BARH() asm volatile("bar.sync %0, 128;" :: "r"(barid) : "memory")

    for (int t = 0; t < TT; t++) {
        // stage x_t, prefetch x_{t+1}
        if (xload) s.xs[half][sb][sk] = xv;
        BARH();                                   // #1: xs + prev h1 visible
        if (xload && (t + 1 < TT)) xv = xptr[(size_t)(t + 1) * II];

        // ---- layer 0 GEMM: gates0 = Wx0*x + Wh0*h0 + b0 ----
        ull acc[NB];
#pragma unroll
        for (int b = 0; b < NB; b++) acc[b] = b0p;
        gemm_part<4, 8, 16>(acc, xsv, wx0);
        gemm_part<8, 16, HH>(acc, h0v, wh0);
#pragma unroll
        for (int b = 0; b < NB; b++) gs[row * GSTR + b] = hadd2(acc[b]);
        BARH();                                   // #2: gates0 visible

        // ---- layer 0 elementwise ----
#pragma unroll
        for (int s2 = 0; s2 < 2; s2++) {
            int b = eb + 4 * s2;
            float gi = gs[(eu)      * GSTR + b];
            float gf = gs[(eu + 32) * GSTR + b];
            float gg = gs[(eu + 64) * GSTR + b];
            float go = gs[(eu + 96) * GSTR + b];
            float ig = sigf(gi), fg = sigf(gf), gv = tanh_f(gg), og = sigf(go);
            c0[s2] = fmaf(fg, c0[s2], ig * gv);
            s.h0[half][b][eu] = og * tanh_f(c0[s2]);
        }
        BARH();                                   // #3: new h0 visible

        // ---- layer 1 GEMM: gates1 = Wx1*h0new + Wh1*h1 + b1 ----
#pragma unroll
        for (int b = 0; b < NB; b++) acc[b] = b1p;
        gemm_part<8, 16, HH>(acc, h0v, wx1);
        gemm_part<8, 16, HH>(acc, h1v, wh1);
#pragma unroll
        for (int b = 0; b < NB; b++) gs[row * GSTR + b] = hadd2(acc[b]);
        BARH();                                   // #4: gates1 visible

        // ---- layer 1 elementwise ----
#pragma unroll
        for (int s2 = 0; s2 < 2; s2++) {
            int b = eb + 4 * s2;
            float gi = gs[(eu)      * GSTR + b];
            float gf = gs[(eu + 32) * GSTR + b];
            float gg = gs[(eu + 64) * GSTR + b];
            float go = gs[(eu + 96) * GSTR + b];
            float ig = sigf(gi), fg = sigf(gf), gv = tanh_f(gg), og = sigf(go);
            c1[s2] = fmaf(fg, c1[s2], ig * gv);
            s.h1[half][b][eu] = og * tanh_f(c1[s2]);
        }
        // next iteration's BARH #1 orders these writes before L1 reads
    }
    BARH();

    // ---- classifier head: hidden = relu(h1 @ Wc1^T + bc1); out = hidden @ Wc2^T + bc2
    {
        int hj = lt & 31, hb = lt >> 5;
#pragma unroll
        for (int s2 = 0; s2 < 2; s2++) {
            int b = hb + 4 * s2;
            float a = bc1[hj];
#pragma unroll
            for (int k = 0; k < HH; k++)
                a = fmaf(s.h1[half][b][k], Wc1[hj * HH + k], a);
            gs[hj * GSTR + b] = fmaxf(a, 0.0f);   // reuse gates as hidden[j][b]
        }
    }
    BARH();
    if (lt < NB * NC) {
        int b = lt / NC, c = lt - b * NC;
        float o = bc2[c];
#pragma unroll
        for (int j = 0; j < HH; j++)
            o = fmaf(gs[j * GSTR + b], Wc2[c * HH + j], o);
        out[(size_t)(bbase + b) * NC + c] = o;
    }
#undef BARH
}

extern "C" void kernel_launch(void* const* d_in, const int* in_sizes, int n_in,
                              void* d_out, int out_size) {
    const float* x    = (const float*)d_in[0];
    const float* Wih0 = (const float*)d_in[1];
    const float* Whh0 = (const float*)d_in[2];
    const float* bih0 = (const float*)d_in[3];
    const float* bhh0 = (const float*)d_in[4];
    const float* Wih1 = (const float*)d_in[5];
    const float* Whh1 = (const float*)d_in[6];
    const float* bih1 = (const float*)d_in[7];
    const float* bhh1 = (const float*)d_in[8];
    const float* Wc1  = (const float*)d_in[9];
    const float* bc1  = (const float*)d_in[10];
    const float* Wc2  = (const float*)d_in[11];
    const float* bc2  = (const float*)d_in[12];
    float* out = (float*)d_out;

    lstm_fused_kernel<<<BB / 16, 256>>>(
        x, Wih0, Whh0, bih0, bhh0, Wih1, Whh1, bih1, bhh1,
        Wc1, bc1, Wc2, bc2, out);
}

// round 4
// speedup vs baseline: 1.4150x; 1.0014x over previous
#include <cuda_runtime.h>

// 2-layer LSTM (B=2048, T=1000, I=13, H=32) + Linear(32)->ReLU->Linear(3).
// 128 blocks x 256 threads. Block = two independent 8-batch halves.
// NEW vs R2: the halves are locked into ANTI-PHASE by a shared barrier
// (bar 3, 256 threads) + a one-layer rotation of half 1's loop body, so one
// half's GEMM (FMA/LDS) overlaps the other half's elementwise (MUFU) and
// barrier waits instead of contending for the same pipe.

#define BB    2048
#define TT    1000
#define II    13
#define HH    32
#define NC    3
#define NB    8            // batches per half
#define GSTR  9            // gate smem row stride (coprime with 32 banks)

typedef unsigned long long ull;

struct alignas(16) Smem {
    float xs[2][NB][16];        // x_t staged, k padded 13->16 (zeros)
    float h0[2][NB][HH];
    float h1[2][NB][HH];
    float gates[2][128 * GSTR]; // [gate_row][batch], stride 9
};

__device__ __forceinline__ ull ffma2(ull a, ull b, ull c) {
    ull d;
    asm("fma.rn.f32x2 %0, %1, %2, %3;" : "=l"(d) : "l"(a), "l"(b), "l"(c));
    return d;
}
__device__ __forceinline__ ull packf2(float lo, float hi) {
    ull r;
    asm("mov.b64 %0, {%1, %2};" : "=l"(r) : "f"(lo), "f"(hi));
    return r;
}
__device__ __forceinline__ float hadd2(ull a) {
    float lo, hi;
    asm("mov.b64 {%0, %1}, %2;" : "=f"(lo), "=f"(hi) : "l"(a));
    return lo + hi;
}
__device__ __forceinline__ ull d2l(double d) { return __double_as_longlong(d); }

__device__ __forceinline__ float sigf(float v) {
    float e = __expf(-v);
    return __fdividef(1.0f, 1.0f + e);
}
__device__ __forceinline__ float tanh_f(float v) {
    v = fminf(12.0f, fmaxf(-12.0f, v));
    float e = __expf(-2.0f * v);
    return __fdividef(1.0f - e, 1.0f + e);
}

template <int NC4, int NW, int BSTR>
__device__ __forceinline__ void gemm_part(ull (&acc)[NB], const float* vbase,
                                          const ull (&w)[NW]) {
#pragma unroll
    for (int c = 0; c < NC4; c++) {
#pragma unroll
        for (int b = 0; b < NB; b++) {
            double2 v = *reinterpret_cast<const double2*>(vbase + b * BSTR + c * 4);
            acc[b] = ffma2(d2l(v.x), w[2 * c + 0], acc[b]);
            acc[b] = ffma2(d2l(v.y), w[2 * c + 1], acc[b]);
        }
    }
}

__global__ void __launch_bounds__(256, 1)
lstm_fused_kernel(const float* __restrict__ x,
                  const float* __restrict__ Wih0, const float* __restrict__ Whh0,
                  const float* __restrict__ bih0, const float* __restrict__ bhh0,
                  const float* __restrict__ Wih1, const float* __restrict__ Whh1,
                  const float* __restrict__ bih1, const float* __restrict__ bhh1,
                  const float* __restrict__ Wc1,  const float* __restrict__ bc1,
                  const float* __restrict__ Wc2,  const float* __restrict__ bc2,
                  float* __restrict__ out) {
    __shared__ Smem s;
    const int tid  = threadIdx.x;
    const int half = tid >> 7;          // 0 or 1
    const int lt   = tid & 127;         // local thread = gate row
    const int bbase = blockIdx.x * 16 + half * NB;

    // ---- zero state region ----
    {
        float* zp = &s.xs[0][0][0];
        const int zn = (int)((sizeof(s.xs) + sizeof(s.h0) + sizeof(s.h1)) / 4);
        for (int i = tid; i < zn; i += 256) zp[i] = 0.0f;
    }

    // ---- register-resident weights, pre-packed as k-pairs ----
    const int row = lt;
    ull wx0[8], wh0[16], wx1[16], wh1[16];
#pragma unroll
    for (int p = 0; p < 8; p++) {
        float lo = (2 * p     < II) ? Wih0[row * II + 2 * p]     : 0.0f;
        float hi = (2 * p + 1 < II) ? Wih0[row * II + 2 * p + 1] : 0.0f;
        wx0[p] = packf2(lo, hi);
    }
#pragma unroll
    for (int p = 0; p < 16; p++) {
        wh0[p] = packf2(Whh0[row * HH + 2 * p], Whh0[row * HH + 2 * p + 1]);
        wx1[p] = packf2(Wih1[row * HH + 2 * p], Wih1[row * HH + 2 * p + 1]);
        wh1[p] = packf2(Whh1[row * HH + 2 * p], Whh1[row * HH + 2 * p + 1]);
    }
    const ull b0p = packf2(bih0[row] + bhh0[row], 0.0f);
    const ull b1p = packf2(bih1[row] + bhh1[row], 0.0f);

    // ---- x staging map ----
    const int sb = lt >> 4, sk = lt & 15;
    const bool xload = (sk < II);
    const float* xptr = x + (size_t)(bbase + sb) * TT * II + sk;
    float xv = xload ? xptr[0] : 0.0f;

    // ---- elementwise map ----
    const int eu = lt & 31;
    const int eb = lt >> 5;
    float c0[2] = {0.f, 0.f}, c1[2] = {0.f, 0.f};

    float* gs = s.gates[half];
    const float* h0v = &s.h0[half][0][0];
    const float* h1v = &s.h1[half][0][0];
    const float* xsv = &s.xs[half][0][0];
    const int barid = half + 1;

    ull acc[NB];

    __syncthreads();

#define BARH() asm volatile("bar.sync %0, 128;" :: "r"(barid) : "memory")
#define LOCK() asm volatile("bar.sync 3, 256;" ::: "memory")

#define PH_STAGE() do { if (xload) s.xs[half][sb][sk] = xv; } while (0)
#define PH_PREF(tn) do { if (xload && (tn) < TT) xv = xptr[(size_t)(tn) * II]; } while (0)

#define PH_G0() do {                                                        \
    _Pragma("unroll") for (int b = 0; b < NB; b++) acc[b] = b0p;            \
    gemm_part<4, 8, 16>(acc, xsv, wx0);                                     \
    gemm_part<8, 16, HH>(acc, h0v, wh0);                                    \
    _Pragma("unroll") for (int b = 0; b < NB; b++)                          \
        gs[row * GSTR + b] = hadd2(acc[b]);                                 \
} while (0)

#define PH_E0() do {                                                        \
    _Pragma("unroll") for (int s2 = 0; s2 < 2; s2++) {                      \
        int b = eb + 4 * s2;                                                \
        float gi = gs[(eu)      * GSTR + b];                                \
        float gf = gs[(eu + 32) * GSTR + b];                                \
        float gg = gs[(eu + 64) * GSTR + b];                                \
        float go = gs[(eu + 96) * GSTR + b];                                \
        float ig = sigf(gi), fg = sigf(gf), gv = tanh_f(gg), og = sigf(go); \
        c0[s2] = fmaf(fg, c0[s2], ig * gv);                                 \
        s.h0[half][b][eu] = og * tanh_f(c0[s2]);                            \
    }                                                                       \
} while (0)

#define PH_G1() do {                                                        \
    _Pragma("unroll") for (int b = 0; b < NB; b++) acc[b] = b1p;            \
    gemm_part<8, 16, HH>(acc, h0v, wx1);                                    \
    gemm_part<8, 16, HH>(acc, h1v, wh1);                                    \
    _Pragma("unroll") for (int b = 0; b < NB; b++)                          \
        gs[row * GSTR + b] = hadd2(acc[b]);                                 \
} while (0)

#define PH_E1() do {                                                        \
    _Pragma("unroll") for (int s2 = 0; s2 < 2; s2++) {                      \
        int b = eb + 4 * s2;                                                \
        float gi = gs[(eu)      * GSTR + b];                                \
        float gf = gs[(eu + 32) * GSTR + b];                                \
        float gg = gs[(eu + 64) * GSTR + b];                                \
        float go = gs[(eu + 96) * GSTR + b];                                \
        float ig = sigf(gi), fg = sigf(gf), gv = tanh_f(gg), og = sigf(go); \
        c1[s2] = fmaf(fg, c1[s2], ig * gv);                                 \
        s.h1[half][b][eu] = og * tanh_f(c1[s2]);                            \
    }                                                                       \
} while (0)

    if (half == 0) {
        // phase order per step: STAGE G0 E0 [LOCK] G1 E1
        for (int t = 0; t < TT; t++) {
            PH_STAGE(); BARH(); PH_PREF(t + 1);
            PH_G0();    BARH();
            PH_E0();    BARH();
            LOCK();
            PH_G1();    BARH();
            PH_E1();
            // loop-top BARH orders h1/E1 writes before next reads
        }
        BARH();
    } else {
        // rotated: prolog STAGE G0, then per step: E0 G1 [LOCK] E1 STAGE G0
        PH_STAGE(); BARH(); PH_PREF(1);
        PH_G0();    BARH();
        for (int t = 0; t < TT; t++) {
            PH_E0();  BARH();
            PH_G1();  LOCK(); BARH();
            PH_E1();
            if (t + 1 < TT) {
                PH_STAGE(); BARH(); PH_PREF(t + 2);
                PH_G0();    BARH();
            }
        }
        BARH();
    }

    // ---- classifier head ----
    {
        int hj = lt & 31, hb = lt >> 5;
#pragma unroll
        for (int s2 = 0; s2 < 2; s2++) {
            int b = hb + 4 * s2;
            float a = bc1[hj];
#pragma unroll
            for (int k = 0; k < HH; k++)
                a = fmaf(s.h1[half][b][k], Wc1[hj * HH + k], a);
            gs[hj * GSTR + b] = fmaxf(a, 0.0f);
        }
    }
    BARH();
    if (lt < NB * NC) {
        int b = lt / NC, c = lt - b * NC;
        float o = bc2[c];
#pragma unroll
        for (int j = 0; j < HH; j++)
            o = fmaf(gs[j * GSTR + b], Wc2[c * HH + j], o);
        out[(size_t)(bbase + b) * NC + c] = o;
    }
#undef BARH
#undef LOCK
#undef PH_STAGE
#undef PH_PREF
#undef PH_G0
#undef PH_E0
#undef PH_G1
#undef PH_E1
}

extern "C" void kernel_launch(void* const* d_in, const int* in_sizes, int n_in,
                              void* d_out, int out_size) {
    const float* x    = (const float*)d_in[0];
    const float* Wih0 = (const float*)d_in[1];
    const float* Whh0 = (const float*)d_in[2];
    const float* bih0 = (const float*)d_in[3];
    const float* bhh0 = (const float*)d_in[4];
    const float* Wih1 = (const float*)d_in[5];
    const float* Whh1 = (const float*)d_in[6];
    const float* bih1 = (const float*)d_in[7];
    const float* bhh1 = (const float*)d_in[8];
    const float* Wc1  = (const float*)d_in[9];
    const float* bc1  = (const float*)d_in[10];
    const float* Wc2  = (const float*)d_in[11];
    const float* bc2  = (const float*)d_in[12];
    float* out = (float*)d_out;

    lstm_fused_kernel<<<BB / 16, 256>>>(
        x, Wih0, Whh0, bih0, bhh0, Wih1, Whh1, bih1, bhh1,
        Wc1, bc1, Wc2, bc2, out);
}

// round 5
// speedup vs baseline: 1.7828x; 1.2600x over previous
#include <cuda_runtime.h>

// 2-layer LSTM (B=2048, T=1000, I=13, H=32) + Linear(32)->ReLU->Linear(3).
// 128 blocks x 256 threads. Block = two independent 8-batch halves.
// NEW vs R3: each half's 128 threads split into an L0 group (64 threads) and
// an L1 group (64 threads), software-pipelined one timestep apart (L1 handles
// tau = t-1 via double-buffered h0). Each thread owns TWO gate rows of ONE
// layer (weights register-resident), so each activation LDS.128 feeds 4
// FFMA2 instead of 2 — halving shared-memory traffic, which R3 profiling
// showed to be the binding resource (L1=66% vs fma=35%).
// Groups interleaved so every SMSP gets one L0 warp + one L1 warp.

#define BB    2048
#define TT    1000
#define II    13
#define HH    32
#define NC    3
#define NB    8
#define GSTR  9            // gate smem row stride (coprime with 32 banks)

typedef unsigned long long ull;

struct alignas(16) Smem {
    float xs[2][2][NB][16];       // [half][parity][b][k], k padded 13->16
    float h0[2][2][NB][HH];       // [half][parity][b][k] double-buffered
    float h1[2][NB][HH];          // [half][b][k]
    float gates[2][2][128 * GSTR];// [half][layer][row*GSTR + b]
};

__device__ __forceinline__ ull ffma2(ull a, ull b, ull c) {
    ull d;
    asm("fma.rn.f32x2 %0, %1, %2, %3;" : "=l"(d) : "l"(a), "l"(b), "l"(c));
    return d;
}
__device__ __forceinline__ ull packf2(float lo, float hi) {
    ull r;
    asm("mov.b64 %0, {%1, %2};" : "=l"(r) : "f"(lo), "f"(hi));
    return r;
}
__device__ __forceinline__ float hadd2(ull a) {
    float lo, hi;
    asm("mov.b64 {%0, %1}, %2;" : "=f"(lo), "=f"(hi) : "l"(a));
    return lo + hi;
}
__device__ __forceinline__ ull d2l(double d) { return __double_as_longlong(d); }

__device__ __forceinline__ float sigf(float v) {
    float e = __expf(-v);
    return __fdividef(1.0f, 1.0f + e);
}
__device__ __forceinline__ float tanh_f(float v) {
    v = fminf(12.0f, fmaxf(-12.0f, v));
    float e = __expf(-2.0f * v);
    return __fdividef(1.0f - e, 1.0f + e);
}

// acc[i][b] += sum over NC4 float4-chunks: v-pairs * w{i}-pairs (f32x2).
// One LDS.128 feeds 4 FFMA2 (2 rows x 2 k-pairs).
template <int NC4, int BSTR>
__device__ __forceinline__ void gemm2(ull (&acc)[2][NB], const float* __restrict__ vb,
                                      const ull (&w0)[16], const ull (&w1)[16]) {
#pragma unroll
    for (int c = 0; c < NC4; c++) {
#pragma unroll
        for (int b = 0; b < NB; b++) {
            double2 v = *reinterpret_cast<const double2*>(vb + b * BSTR + c * 4);
            ull vx = d2l(v.x), vy = d2l(v.y);
            acc[0][b] = ffma2(vx, w0[2 * c],     acc[0][b]);
            acc[0][b] = ffma2(vy, w0[2 * c + 1], acc[0][b]);
            acc[1][b] = ffma2(vx, w1[2 * c],     acc[1][b]);
            acc[1][b] = ffma2(vy, w1[2 * c + 1], acc[1][b]);
        }
    }
}

__global__ void __launch_bounds__(256, 1)
lstm_fused_kernel(const float* __restrict__ x,
                  const float* __restrict__ Wih0, const float* __restrict__ Whh0,
                  const float* __restrict__ bih0, const float* __restrict__ bhh0,
                  const float* __restrict__ Wih1, const float* __restrict__ Whh1,
                  const float* __restrict__ bih1, const float* __restrict__ bhh1,
                  const float* __restrict__ Wc1,  const float* __restrict__ bc1,
                  const float* __restrict__ Wc2,  const float* __restrict__ bc2,
                  float* __restrict__ out) {
    extern __shared__ char smem_raw[];
    Smem& s = *reinterpret_cast<Smem*>(smem_raw);
    const int tid  = threadIdx.x;
    const int half = tid >> 7;
    const int lt   = tid & 127;
    const int grp  = lt >> 6;          // physical group within half
    const int gl   = lt & 63;          // lane within group
    // group->layer map interleaved across halves for SMSP FMA balance:
    const bool is_l0 = ((grp ^ half) == 0);
    const int bbase = blockIdx.x * 16 + half * NB;

    // ---- zero state (xs, h0, h1 contiguous at struct start) ----
    {
        float* zp = reinterpret_cast<float*>(&s);
        const int zn = (int)((sizeof(s.xs) + sizeof(s.h0) + sizeof(s.h1)) / 4);
        for (int i = tid; i < zn; i += 256) zp[i] = 0.0f;
    }
    // ---- stage x(0) into xs[*][0] ----
    for (int i = tid; i < 2 * NB * II; i += 256) {
        int hf = i / (NB * II), r = i % (NB * II), b = r / II, k = r % II;
        s.xs[hf][0][b][k] =
            x[(size_t)(blockIdx.x * 16 + hf * NB + b) * TT * II + k];
    }

    // ---- register-resident weights: 2 rows (gl, gl+64) of ONE layer ----
    ull wA[2][16], wB[2][16];
    ull biasA, biasB;
    if (is_l0) {
#pragma unroll
        for (int i = 0; i < 2; i++) {
            int r = gl + i * 64;
#pragma unroll
            for (int p = 0; p < 8; p++) {
                float lo = (2 * p     < II) ? Wih0[r * II + 2 * p]     : 0.0f;
                float hi = (2 * p + 1 < II) ? Wih0[r * II + 2 * p + 1] : 0.0f;
                wA[i][p] = packf2(lo, hi);
            }
#pragma unroll
            for (int p = 0; p < 16; p++)
                wB[i][p] = packf2(Whh0[r * HH + 2 * p], Whh0[r * HH + 2 * p + 1]);
        }
        biasA = packf2(bih0[gl] + bhh0[gl], 0.0f);
        biasB = packf2(bih0[gl + 64] + bhh0[gl + 64], 0.0f);
    } else {
#pragma unroll
        for (int i = 0; i < 2; i++) {
            int r = gl + i * 64;
#pragma unroll
            for (int p = 0; p < 16; p++) {
                wA[i][p] = packf2(Wih1[r * HH + 2 * p], Wih1[r * HH + 2 * p + 1]);
                wB[i][p] = packf2(Whh1[r * HH + 2 * p], Whh1[r * HH + 2 * p + 1]);
            }
        }
        biasA = packf2(bih1[gl] + bhh1[gl], 0.0f);
        biasB = packf2(bih1[gl + 64] + bhh1[gl + 64], 0.0f);
    }

    // ---- elementwise map: thread -> unit eu, batches ebb..ebb+3 ----
    const int eu  = gl & 31;
    const int ebb = (gl >> 5) * 4;
    float cst[4] = {0.f, 0.f, 0.f, 0.f};

    float* gs = s.gates[half][is_l0 ? 0 : 1];
    const int hbid = 1 + half;
    const int gbid = 3 + half * 2 + grp;

    // x staging slots for L0 threads: slots gl and gl+64 -> (b, k)
    const int pb0 = gl >> 4,        pk0 = gl & 15;
    const int pb1 = (gl + 64) >> 4, pk1 = (gl + 64) & 15;
    const bool pv0 = (pk0 < II), pv1 = (pk1 < II);
    const float* xbase = x + (size_t)bbase * TT * II;

    __syncthreads();

#define HBAR() asm volatile("bar.sync %0, 128;" :: "r"(hbid) : "memory")
#define GBAR() asm volatile("bar.sync %0, 64;"  :: "r"(gbid) : "memory")

    for (int t = 0; t <= TT; t++) {
        HBAR();   // step boundary: orders all prior h/x writes for both groups
        if (is_l0) {
            // prefetch x(t+1)
            float xn0 = 0.f, xn1 = 0.f;
            if (t + 1 < TT) {
                if (pv0) xn0 = xbase[(size_t)pb0 * TT * II + (size_t)(t + 1) * II + pk0];
                if (pv1) xn1 = xbase[(size_t)pb1 * TT * II + (size_t)(t + 1) * II + pk1];
            }
            if (t < TT) {
                const float* xsv = &s.xs[half][t & 1][0][0];
                const float* h0v = &s.h0[half][t & 1][0][0];
                ull acc[2][NB];
#pragma unroll
                for (int b = 0; b < NB; b++) { acc[0][b] = biasA; acc[1][b] = biasB; }
                gemm2<4, 16>(acc, xsv, wA[0], wA[1]);
                gemm2<8, HH>(acc, h0v, wB[0], wB[1]);
#pragma unroll
                for (int b = 0; b < NB; b++) {
                    gs[gl * GSTR + b]        = hadd2(acc[0][b]);
                    gs[(gl + 64) * GSTR + b] = hadd2(acc[1][b]);
                }
            }
            GBAR();
            if (t < TT) {
#pragma unroll
                for (int j = 0; j < 4; j++) {
                    int b = ebb + j;
                    float gi = gs[(eu)      * GSTR + b];
                    float gf = gs[(eu + 32) * GSTR + b];
                    float gg = gs[(eu + 64) * GSTR + b];
                    float go = gs[(eu + 96) * GSTR + b];
                    float ig = sigf(gi), fg = sigf(gf);
                    float gv = tanh_f(gg), og = sigf(go);
                    cst[j] = fmaf(fg, cst[j], ig * gv);
                    s.h0[half][(t + 1) & 1][b][eu] = og * tanh_f(cst[j]);
                }
                // commit staged x(t+1)
                if (t + 1 < TT) {
                    if (pv0) s.xs[half][(t + 1) & 1][pb0][pk0] = xn0;
                    if (pv1) s.xs[half][(t + 1) & 1][pb1][pk1] = xn1;
                }
            }
        } else {
            // L1 group processes tau = t-1
            if (t > 0) {
                const float* h0v = &s.h0[half][t & 1][0][0];   // h0(tau)
                const float* h1v = &s.h1[half][0][0];          // h1(tau-1)
                ull acc[2][NB];
#pragma unroll
                for (int b = 0; b < NB; b++) { acc[0][b] = biasA; acc[1][b] = biasB; }
                gemm2<8, HH>(acc, h0v, wA[0], wA[1]);
                gemm2<8, HH>(acc, h1v, wB[0], wB[1]);
#pragma unroll
                for (int b = 0; b < NB; b++) {
                    gs[gl * GSTR + b]        = hadd2(acc[0][b]);
                    gs[(gl + 64) * GSTR + b] = hadd2(acc[1][b]);
                }
            }
            GBAR();
            if (t > 0) {
#pragma unroll
                for (int j = 0; j < 4; j++) {
                    int b = ebb + j;
                    float gi = gs[(eu)      * GSTR + b];
                    float gf = gs[(eu + 32) * GSTR + b];
                    float gg = gs[(eu + 64) * GSTR + b];
                    float go = gs[(eu + 96) * GSTR + b];
                    float ig = sigf(gi), fg = sigf(gf);
                    float gv = tanh_f(gg), og = sigf(go);
                    cst[j] = fmaf(fg, cst[j], ig * gv);
                    s.h1[half][b][eu] = og * tanh_f(cst[j]);
                }
            }
        }
    }
    HBAR();   // h1(T-1) visible to whole half

    // ---- classifier head ----
    {
        int hj = lt & 31, hb = lt >> 5;
        float* hs = s.gates[half][0];   // scratch
#pragma unroll
        for (int s2 = 0; s2 < 2; s2++) {
            int b = hb + 4 * s2;
            float a = bc1[hj];
#pragma unroll
            for (int k = 0; k < HH; k++)
                a = fmaf(s.h1[half][b][k], Wc1[hj * HH + k], a);
            hs[hj * GSTR + b] = fmaxf(a, 0.0f);
        }
    }
    HBAR();
    if (lt < NB * NC) {
        int b = lt / NC, c = lt - b * NC;
        float* hs = s.gates[half][0];
        float o = bc2[c];
#pragma unroll
        for (int j = 0; j < HH; j++)
            o = fmaf(hs[j * GSTR + b], Wc2[c * HH + j], o);
        out[(size_t)(bbase + b) * NC + c] = o;
    }
#undef HBAR
#undef GBAR
}

extern "C" void kernel_launch(void* const* d_in, const int* in_sizes, int n_in,
                              void* d_out, int out_size) {
    const float* x    = (const float*)d_in[0];
    const float* Wih0 = (const float*)d_in[1];
    const float* Whh0 = (const float*)d_in[2];
    const float* bih0 = (const float*)d_in[3];
    const float* bhh0 = (const float*)d_in[4];
    const float* Wih1 = (const float*)d_in[5];
    const float* Whh1 = (const float*)d_in[6];
    const float* bih1 = (const float*)d_in[7];
    const float* bhh1 = (const float*)d_in[8];
    const float* Wc1  = (const float*)d_in[9];
    const float* bc1  = (const float*)d_in[10];
    const float* Wc2  = (const float*)d_in[11];
    const float* bc2  = (const float*)d_in[12];
    float* out = (float*)d_out;

    cudaFuncSetAttribute(lstm_fused_kernel,
                         cudaFuncAttributeMaxDynamicSharedMemorySize,
                         (int)sizeof(Smem));

    lstm_fused_kernel<<<BB / 16, 256, sizeof(Smem)>>>(
        x, Wih0, Whh0, bih0, bhh0, Wih1, Whh1, bih1, bhh1,
        Wc1, bc1, Wc2, bc2, out);
}

// round 6
// speedup vs baseline: 1.9120x; 1.0724x over previous
#include <cuda_runtime.h>

// 2-layer LSTM (B=2048, T=1000, I=13, H=32) + Linear(32)->ReLU->Linear(3).
// 148 blocks x 256 threads (full chip). Block = two independent 14-batch...
// two 7-batch halves. Each half: L0 group (64 thr) + L1 group (64 thr),
// software-pipelined one step apart over double-buffered h0.
// NEW vs R4: groups are decoupled with producer/consumer bar.arrive/bar.sync
// pairs (A = h0 ready, B = h0 consumed) instead of a full-half barrier, so
// one group's MUFU/elementwise phase overlaps the other's FMA/GEMM phase.
// Grid rebalanced 128->148 blocks (14 batches each, tail padded+guarded).

#define BB    2048
#define TT    1000
#define II    13
#define HH    32
#define NC    3
#define NBH   7            // batches per half
#define BPB   14           // batches per block
#define GRIDN 148
#define GSTR  9            // gate smem row stride (coprime with 32 banks)

typedef unsigned long long ull;

struct alignas(16) Smem {
    float xs[2][2][NBH][16];        // [half][parity][b][k], k padded 13->16
    float h0[2][2][NBH][HH];        // [half][parity][b][k]
    float h1[2][NBH][HH];           // [half][b][k]
    float gates[2][2][128 * GSTR];  // [half][group-layer][row*GSTR + b]
};

__device__ __forceinline__ ull ffma2(ull a, ull b, ull c) {
    ull d;
    asm("fma.rn.f32x2 %0, %1, %2, %3;" : "=l"(d) : "l"(a), "l"(b), "l"(c));
    return d;
}
__device__ __forceinline__ ull packf2(float lo, float hi) {
    ull r;
    asm("mov.b64 %0, {%1, %2};" : "=l"(r) : "f"(lo), "f"(hi));
    return r;
}
__device__ __forceinline__ float hadd2(ull a) {
    float lo, hi;
    asm("mov.b64 {%0, %1}, %2;" : "=f"(lo), "=f"(hi) : "l"(a));
    return lo + hi;
}
__device__ __forceinline__ ull d2l(double d) { return __double_as_longlong(d); }

__device__ __forceinline__ float sigf(float v) {
    float e = __expf(-v);
    return __fdividef(1.0f, 1.0f + e);
}
__device__ __forceinline__ float tanh_f(float v) {
    v = fminf(12.0f, fmaxf(-12.0f, v));
    float e = __expf(-2.0f * v);
    return __fdividef(1.0f - e, 1.0f + e);
}

// acc[i][b] += sum over NC4 float4-chunks: v-pairs * w{i}-pairs (f32x2).
template <int NC4, int BSTR>
__device__ __forceinline__ void gemm2(ull (&acc)[2][NBH], const float* __restrict__ vb,
                                      const ull (&w0)[16], const ull (&w1)[16]) {
#pragma unroll
    for (int c = 0; c < NC4; c++) {
#pragma unroll
        for (int b = 0; b < NBH; b++) {
            double2 v = *reinterpret_cast<const double2*>(vb + b * BSTR + c * 4);
            ull vx = d2l(v.x), vy = d2l(v.y);
            acc[0][b] = ffma2(vx, w0[2 * c],     acc[0][b]);
            acc[0][b] = ffma2(vy, w0[2 * c + 1], acc[0][b]);
            acc[1][b] = ffma2(vx, w1[2 * c],     acc[1][b]);
            acc[1][b] = ffma2(vy, w1[2 * c + 1], acc[1][b]);
        }
    }
}

__global__ void __launch_bounds__(256, 1)
lstm_fused_kernel(const float* __restrict__ x,
                  const float* __restrict__ Wih0, const float* __restrict__ Whh0,
                  const float* __restrict__ bih0, const float* __restrict__ bhh0,
                  const float* __restrict__ Wih1, const float* __restrict__ Whh1,
                  const float* __restrict__ bih1, const float* __restrict__ bhh1,
                  const float* __restrict__ Wc1,  const float* __restrict__ bc1,
                  const float* __restrict__ Wc2,  const float* __restrict__ bc2,
                  float* __restrict__ out) {
    __shared__ Smem s;
    const int tid  = threadIdx.x;
    const int half = tid >> 7;
    const int lt   = tid & 127;
    const int grp  = lt >> 6;          // physical group within half
    const int gl   = lt & 63;
    const bool is_l0 = ((grp ^ half) == 0);   // SMSP-balanced layer map
    const int bbase = blockIdx.x * BPB + half * NBH;

    // ---- zero state (xs, h0, h1 contiguous at struct start) ----
    {
        float* zp = reinterpret_cast<float*>(&s);
        const int zn = (int)((sizeof(s.xs) + sizeof(s.h0) + sizeof(s.h1)) / 4);
        for (int i = tid; i < zn; i += 256) zp[i] = 0.0f;
    }
    // ---- stage x(0) (batch-clamped for tail blocks) ----
    for (int i = tid; i < 2 * NBH * II; i += 256) {
        int hf = i / (NBH * II), r = i % (NBH * II), b = r / II, k = r % II;
        int gb = blockIdx.x * BPB + hf * NBH + b;
        if (gb > BB - 1) gb = BB - 1;
        s.xs[hf][0][b][k] = x[(size_t)gb * TT * II + k];
    }

    // ---- register-resident weights: rows (gl, gl+64) of ONE layer ----
    ull wA[2][16], wB[2][16];
    ull biasA, biasB;
    if (is_l0) {
#pragma unroll
        for (int i = 0; i < 2; i++) {
            int r = gl + i * 64;
#pragma unroll
            for (int p = 0; p < 8; p++) {
                float lo = (2 * p     < II) ? Wih0[r * II + 2 * p]     : 0.0f;
                float hi = (2 * p + 1 < II) ? Wih0[r * II + 2 * p + 1] : 0.0f;
                wA[i][p] = packf2(lo, hi);
            }
#pragma unroll
            for (int p = 0; p < 16; p++)
                wB[i][p] = packf2(Whh0[r * HH + 2 * p], Whh0[r * HH + 2 * p + 1]);
        }
        biasA = packf2(bih0[gl] + bhh0[gl], 0.0f);
        biasB = packf2(bih0[gl + 64] + bhh0[gl + 64], 0.0f);
    } else {
#pragma unroll
        for (int i = 0; i < 2; i++) {
            int r = gl + i * 64;
#pragma unroll
            for (int p = 0; p < 16; p++) {
                wA[i][p] = packf2(Wih1[r * HH + 2 * p], Wih1[r * HH + 2 * p + 1]);
                wB[i][p] = packf2(Whh1[r * HH + 2 * p], Whh1[r * HH + 2 * p + 1]);
            }
        }
        biasA = packf2(bih1[gl] + bhh1[gl], 0.0f);
        biasB = packf2(bih1[gl + 64] + bhh1[gl + 64], 0.0f);
    }

    // ---- elementwise map: unit eu, batch base ebb (0 or 4) ----
    const int eu  = gl & 31;
    const int ebb = (gl >> 5) * 4;
    float cst[4] = {0.f, 0.f, 0.f, 0.f};

    float* gs = s.gates[half][grp];

    // ---- x staging slots (L0 threads): slots gl and gl+64 ----
    const int pb0 = gl >> 4,        pk0 = gl & 15;
    const int pb1 = (gl + 64) >> 4, pk1 = (gl + 64) & 15;
    const bool pv0 = (pb0 < NBH) && (pk0 < II);
    const bool pv1 = (pb1 < NBH) && (pk1 < II);
    int cb0 = bbase + pb0; if (cb0 > BB - 1) cb0 = BB - 1;
    int cb1 = bbase + pb1; if (cb1 > BB - 1) cb1 = BB - 1;
    const float* xc0 = x + (size_t)cb0 * TT * II + pk0;
    const float* xc1 = x + (size_t)cb1 * TT * II + pk1;

    const int idA = 1 + half;                 // h0-ready barrier
    const int idB = 3 + half;                 // h0-consumed barrier
    const int idG = 5 + half * 2 + grp;       // intra-group barrier

    __syncthreads();

#define ARRV(id) asm volatile("bar.arrive %0, 128;" :: "r"(id) : "memory")
#define WAIT(id) asm volatile("bar.sync %0, 128;"   :: "r"(id) : "memory")
#define GBAR()   asm volatile("bar.sync %0, 64;"    :: "r"(idG) : "memory")

    for (int t = 0; t <= TT; t++) {
        if (is_l0) {
            if (t < TT) {
                if (t >= 2) { WAIT(idB); } else { GBAR(); }   // h0 buf free + L0 rendezvous
                float xn0 = 0.f, xn1 = 0.f;
                if (t + 1 < TT) {
                    if (pv0) xn0 = xc0[(size_t)(t + 1) * II];
                    if (pv1) xn1 = xc1[(size_t)(t + 1) * II];
                }
                const float* xsv = &s.xs[half][t & 1][0][0];
                const float* h0v = &s.h0[half][t & 1][0][0];
                ull acc[2][NBH];
#pragma unroll
                for (int b = 0; b < NBH; b++) { acc[0][b] = biasA; acc[1][b] = biasB; }
                gemm2<4, 16>(acc, xsv, wA[0], wA[1]);
                gemm2<8, HH>(acc, h0v, wB[0], wB[1]);
#pragma unroll
                for (int b = 0; b < NBH; b++) {
                    gs[gl * GSTR + b]        = hadd2(acc[0][b]);
                    gs[(gl + 64) * GSTR + b] = hadd2(acc[1][b]);
                }
                GBAR();                                        // gates ready
#pragma unroll
                for (int j = 0; j < 4; j++) {
                    int b = ebb + j;
                    if (b < NBH) {
                        float gi = gs[(eu)      * GSTR + b];
                        float gf = gs[(eu + 32) * GSTR + b];
                        float gg = gs[(eu + 64) * GSTR + b];
                        float go = gs[(eu + 96) * GSTR + b];
                        float ig = sigf(gi), fg = sigf(gf);
                        float gv = tanh_f(gg), og = sigf(go);
                        cst[j] = fmaf(fg, cst[j], ig * gv);
                        s.h0[half][(t + 1) & 1][b][eu] = og * tanh_f(cst[j]);
                    }
                }
                if (t + 1 < TT) {
                    if (pv0) s.xs[half][(t + 1) & 1][pb0][pk0] = xn0;
                    if (pv1) s.xs[half][(t + 1) & 1][pb1][pk1] = xn1;
                }
                ARRV(idA);                                     // h0(t) published
            }
        } else {
            if (t > 0) {
                WAIT(idA);                 // h0[t&1] ready + L1 rendezvous
                const float* h0v = &s.h0[half][t & 1][0][0];
                const float* h1v = &s.h1[half][0][0];
                ull acc[2][NBH];
#pragma unroll
                for (int b = 0; b < NBH; b++) { acc[0][b] = biasA; acc[1][b] = biasB; }
                gemm2<8, HH>(acc, h0v, wA[0], wA[1]);
                gemm2<8, HH>(acc, h1v, wB[0], wB[1]);
#pragma unroll
                for (int b = 0; b < NBH; b++) {
                    gs[gl * GSTR + b]        = hadd2(acc[0][b]);
                    gs[(gl + 64) * GSTR + b] = hadd2(acc[1][b]);
                }
                ARRV(idB);                 // h0 buffer consumed -> release L0
                GBAR();                    // gates ready
#pragma unroll
                for (int j = 0; j < 4; j++) {
                    int b = ebb + j;
                    if (b < NBH) {
                        float gi = gs[(eu)      * GSTR + b];
                        float gf = gs[(eu + 32) * GSTR + b];
                        float gg = gs[(eu + 64) * GSTR + b];
                        float go = gs[(eu + 96) * GSTR + b];
                        float ig = sigf(gi), fg = sigf(gf);
                        float gv = tanh_f(gg), og = sigf(go);
                        cst[j] = fmaf(fg, cst[j], ig * gv);
                        s.h1[half][b][eu] = og * tanh_f(cst[j]);
                    }
                }
            }
        }
    }
    __syncthreads();

    // ---- classifier head ----
    {
        int hj = lt & 31, hb = lt >> 5;
        float* hs = s.gates[half][0];
#pragma unroll
        for (int s2 = 0; s2 < 2; s2++) {
            int b = hb + 4 * s2;
            if (b < NBH) {
                float a = bc1[hj];
#pragma unroll
                for (int k = 0; k < HH; k++)
                    a = fmaf(s.h1[half][b][k], Wc1[hj * HH + k], a);
                hs[hj * GSTR + b] = fmaxf(a, 0.0f);
            }
        }
    }
    __syncthreads();
    if (lt < NBH * NC) {
        int b = lt / NC, c = lt - b * NC;
        if (bbase + b < BB) {
            float* hs = s.gates[half][0];
            float o = bc2[c];
#pragma unroll
            for (int j = 0; j < HH; j++)
                o = fmaf(hs[j * GSTR + b], Wc2[c * HH + j], o);
            out[(size_t)(bbase + b) * NC + c] = o;
        }
    }
#undef ARRV
#undef WAIT
#undef GBAR
}

extern "C" void kernel_launch(void* const* d_in, const int* in_sizes, int n_in,
                              void* d_out, int out_size) {
    const float* x    = (const float*)d_in[0];
    const float* Wih0 = (const float*)d_in[1];
    const float* Whh0 = (const float*)d_in[2];
    const float* bih0 = (const float*)d_in[3];
    const float* bhh0 = (const float*)d_in[4];
    const float* Wih1 = (const float*)d_in[5];
    const float* Whh1 = (const float*)d_in[6];
    const float* bih1 = (const float*)d_in[7];
    const float* bhh1 = (const float*)d_in[8];
    const float* Wc1  = (const float*)d_in[9];
    const float* bc1  = (const float*)d_in[10];
    const float* Wc2  = (const float*)d_in[11];
    const float* bc2  = (const float*)d_in[12];
    float* out = (float*)d_out;

    lstm_fused_kernel<<<GRIDN, 256>>>(
        x, Wih0, Whh0, bih0, bhh0, Wih1, Whh1, bih1, bhh1,
        Wc1, bc1, Wc2, bc2, out);
}

// round 7
// speedup vs baseline: 2.2465x; 1.1750x over previous
#include <cuda_runtime.h>

// 2-layer LSTM (B=2048, T=1000, I=13, H=32) + Linear(32)->ReLU->Linear(3).
// 148 blocks x 256 threads. Block = two independent 7-batch halves; each half
// = L0 group (64 thr) + L1 group (64 thr) software-pipelined one step apart
// over double-buffered h0 with producer/consumer named barriers.
// NEW vs R5: activations use tanh.approx.f32 (1 MUFU op) — sigmoid via the
// tanh identity — halving MUFU traffic and shortening the elementwise
// dependency chains that sit on the L0->L1 handoff critical path.

#define BB    2048
#define TT    1000
#define II    13
#define HH    32
#define NC    3
#define NBH   7            // batches per half
#define BPB   14           // batches per block
#define GRIDN 148
#define GSTR  9            // gate smem row stride (coprime with 32 banks)

typedef unsigned long long ull;

struct alignas(16) Smem {
    float xs[2][2][NBH][16];        // [half][parity][b][k], k padded 13->16
    float h0[2][2][NBH][HH];        // [half][parity][b][k]
    float h1[2][NBH][HH];           // [half][b][k]
    float gates[2][2][128 * GSTR];  // [half][group-layer][row*GSTR + b]
};

__device__ __forceinline__ ull ffma2(ull a, ull b, ull c) {
    ull d;
    asm("fma.rn.f32x2 %0, %1, %2, %3;" : "=l"(d) : "l"(a), "l"(b), "l"(c));
    return d;
}
__device__ __forceinline__ ull packf2(float lo, float hi) {
    ull r;
    asm("mov.b64 %0, {%1, %2};" : "=l"(r) : "f"(lo), "f"(hi));
    return r;
}
__device__ __forceinline__ float hadd2(ull a) {
    float lo, hi;
    asm("mov.b64 {%0, %1}, %2;" : "=f"(lo), "=f"(hi) : "l"(a));
    return lo + hi;
}
__device__ __forceinline__ ull d2l(double d) { return __double_as_longlong(d); }

__device__ __forceinline__ float tanhap(float v) {
    float y;
    asm("tanh.approx.f32 %0, %1;" : "=f"(y) : "f"(v));
    return y;
}
__device__ __forceinline__ float sigf(float v) {
    return fmaf(tanhap(0.5f * v), 0.5f, 0.5f);
}
__device__ __forceinline__ float tanh_f(float v) { return tanhap(v); }

// acc[i][b] += sum over NC4 float4-chunks: v-pairs * w{i}-pairs (f32x2).
template <int NC4, int BSTR>
__device__ __forceinline__ void gemm2(ull (&acc)[2][NBH], const float* __restrict__ vb,
                                      const ull (&w0)[16], const ull (&w1)[16]) {
#pragma unroll
    for (int c = 0; c < NC4; c++) {
#pragma unroll
        for (int b = 0; b < NBH; b++) {
            double2 v = *reinterpret_cast<const double2*>(vb + b * BSTR + c * 4);
            ull vx = d2l(v.x), vy = d2l(v.y);
            acc[0][b] = ffma2(vx, w0[2 * c],     acc[0][b]);
            acc[0][b] = ffma2(vy, w0[2 * c + 1], acc[0][b]);
            acc[1][b] = ffma2(vx, w1[2 * c],     acc[1][b]);
            acc[1][b] = ffma2(vy, w1[2 * c + 1], acc[1][b]);
        }
    }
}

__global__ void __launch_bounds__(256, 1)
lstm_fused_kernel(const float* __restrict__ x,
                  const float* __restrict__ Wih0, const float* __restrict__ Whh0,
                  const float* __restrict__ bih0, const float* __restrict__ bhh0,
                  const float* __restrict__ Wih1, const float* __restrict__ Whh1,
                  const float* __restrict__ bih1, const float* __restrict__ bhh1,
                  const float* __restrict__ Wc1,  const float* __restrict__ bc1,
                  const float* __restrict__ Wc2,  const float* __restrict__ bc2,
                  float* __restrict__ out) {
    __shared__ Smem s;
    const int tid  = threadIdx.x;
    const int half = tid >> 7;
    const int lt   = tid & 127;
    const int grp  = lt >> 6;
    const int gl   = lt & 63;
    const bool is_l0 = ((grp ^ half) == 0);   // SMSP-balanced layer map
    const int bbase = blockIdx.x * BPB + half * NBH;

    // ---- zero state ----
    {
        float* zp = reinterpret_cast<float*>(&s);
        const int zn = (int)((sizeof(s.xs) + sizeof(s.h0) + sizeof(s.h1)) / 4);
        for (int i = tid; i < zn; i += 256) zp[i] = 0.0f;
    }
    // ---- stage x(0) (batch-clamped for tail blocks) ----
    for (int i = tid; i < 2 * NBH * II; i += 256) {
        int hf = i / (NBH * II), r = i % (NBH * II), b = r / II, k = r % II;
        int gb = blockIdx.x * BPB + hf * NBH + b;
        if (gb > BB - 1) gb = BB - 1;
        s.xs[hf][0][b][k] = x[(size_t)gb * TT * II + k];
    }

    // ---- register-resident weights: rows (gl, gl+64) of ONE layer ----
    ull wA[2][16], wB[2][16];
    ull biasA, biasB;
    if (is_l0) {
#pragma unroll
        for (int i = 0; i < 2; i++) {
            int r = gl + i * 64;
#pragma unroll
            for (int p = 0; p < 8; p++) {
                float lo = (2 * p     < II) ? Wih0[r * II + 2 * p]     : 0.0f;
                float hi = (2 * p + 1 < II) ? Wih0[r * II + 2 * p + 1] : 0.0f;
                wA[i][p] = packf2(lo, hi);
            }
#pragma unroll
            for (int p = 0; p < 16; p++)
                wB[i][p] = packf2(Whh0[r * HH + 2 * p], Whh0[r * HH + 2 * p + 1]);
        }
        biasA = packf2(bih0[gl] + bhh0[gl], 0.0f);
        biasB = packf2(bih0[gl + 64] + bhh0[gl + 64], 0.0f);
    } else {
#pragma unroll
        for (int i = 0; i < 2; i++) {
            int r = gl + i * 64;
#pragma unroll
            for (int p = 0; p < 16; p++) {
                wA[i][p] = packf2(Wih1[r * HH + 2 * p], Wih1[r * HH + 2 * p + 1]);
                wB[i][p] = packf2(Whh1[r * HH + 2 * p], Whh1[r * HH + 2 * p + 1]);
            }
        }
        biasA = packf2(bih1[gl] + bhh1[gl], 0.0f);
        biasB = packf2(bih1[gl + 64] + bhh1[gl + 64], 0.0f);
    }

    const int eu  = gl & 31;
    const int ebb = (gl >> 5) * 4;
    float cst[4] = {0.f, 0.f, 0.f, 0.f};

    float* gs = s.gates[half][grp];

    const int pb0 = gl >> 4,        pk0 = gl & 15;
    const int pb1 = (gl + 64) >> 4, pk1 = (gl + 64) & 15;
    const bool pv0 = (pb0 < NBH) && (pk0 < II);
    const bool pv1 = (pb1 < NBH) && (pk1 < II);
    int cb0 = bbase + pb0; if (cb0 > BB - 1) cb0 = BB - 1;
    int cb1 = bbase + pb1; if (cb1 > BB - 1) cb1 = BB - 1;
    const float* xc0 = x + (size_t)cb0 * TT * II + pk0;
    const float* xc1 = x + (size_t)cb1 * TT * II + pk1;

    const int idA = 1 + half;                 // h0-ready
    const int idB = 3 + half;                 // h0-consumed
    const int idG = 5 + half * 2 + grp;       // intra-group

    __syncthreads();

#define ARRV(id) asm volatile("bar.arrive %0, 128;" :: "r"(id) : "memory")
#define WAIT(id) asm volatile("bar.sync %0, 128;"   :: "r"(id) : "memory")
#define GBAR()   asm volatile("bar.sync %0, 64;"    :: "r"(idG) : "memory")

    for (int t = 0; t <= TT; t++) {
        if (is_l0) {
            if (t < TT) {
                if (t >= 2) { WAIT(idB); } else { GBAR(); }
                float xn0 = 0.f, xn1 = 0.f;
                if (t + 1 < TT) {
                    if (pv0) xn0 = xc0[(size_t)(t + 1) * II];
                    if (pv1) xn1 = xc1[(size_t)(t + 1) * II];
                }
                const float* xsv = &s.xs[half][t & 1][0][0];
                const float* h0v = &s.h0[half][t & 1][0][0];
                ull acc[2][NBH];
#pragma unroll
                for (int b = 0; b < NBH; b++) { acc[0][b] = biasA; acc[1][b] = biasB; }
                gemm2<4, 16>(acc, xsv, wA[0], wA[1]);
                gemm2<8, HH>(acc, h0v, wB[0], wB[1]);
#pragma unroll
                for (int b = 0; b < NBH; b++) {
                    gs[gl * GSTR + b]        = hadd2(acc[0][b]);
                    gs[(gl + 64) * GSTR + b] = hadd2(acc[1][b]);
                }
                GBAR();
#pragma unroll
                for (int j = 0; j < 4; j++) {
                    int b = ebb + j;
                    if (b < NBH) {
                        float gi = gs[(eu)      * GSTR + b];
                        float gf = gs[(eu + 32) * GSTR + b];
                        float gg = gs[(eu + 64) * GSTR + b];
                        float go = gs[(eu + 96) * GSTR + b];
                        float ig = sigf(gi), fg = sigf(gf);
                        float gv = tanh_f(gg), og = sigf(go);
                        cst[j] = fmaf(fg, cst[j], ig * gv);
                        s.h0[half][(t + 1) & 1][b][eu] = og * tanh_f(cst[j]);
                    }
                }
                ARRV(idA);                 // h0(t) published (before x commit)
                if (t + 1 < TT) {
                    if (pv0) s.xs[half][(t + 1) & 1][pb0][pk0] = xn0;
                    if (pv1) s.xs[half][(t + 1) & 1][pb1][pk1] = xn1;
                }
            }
        } else {
            if (t > 0) {
                WAIT(idA);
                const float* h0v = &s.h0[half][t & 1][0][0];
                const float* h1v = &s.h1[half][0][0];
                ull acc[2][NBH];
#pragma unroll
                for (int b = 0; b < NBH; b++) { acc[0][b] = biasA; acc[1][b] = biasB; }
                gemm2<8, HH>(acc, h0v, wA[0], wA[1]);
                gemm2<8, HH>(acc, h1v, wB[0], wB[1]);
#pragma unroll
                for (int b = 0; b < NBH; b++) {
                    gs[gl * GSTR + b]        = hadd2(acc[0][b]);
                    gs[(gl + 64) * GSTR + b] = hadd2(acc[1][b]);
                }
                ARRV(idB);
                GBAR();
#pragma unroll
                for (int j = 0; j < 4; j++) {
                    int b = ebb + j;
                    if (b < NBH) {
                        float gi = gs[(eu)      * GSTR + b];
                        float gf = gs[(eu + 32) * GSTR + b];
                        float gg = gs[(eu + 64) * GSTR + b];
                        float go = gs[(eu + 96) * GSTR + b];
                        float ig = sigf(gi), fg = sigf(gf);
                        float gv = tanh_f(gg), og = sigf(go);
                        cst[j] = fmaf(fg, cst[j], ig * gv);
                        s.h1[half][b][eu] = og * tanh_f(cst[j]);
                    }
                }
            }
        }
    }
    __syncthreads();

    // ---- classifier head ----
    {
        int hj = lt & 31, hb = lt >> 5;
        float* hs = s.gates[half][0];
#pragma unroll
        for (int s2 = 0; s2 < 2; s2++) {
            int b = hb + 4 * s2;
            if (b < NBH) {
                float a = bc1[hj];
#pragma unroll
                for (int k = 0; k < HH; k++)
                    a = fmaf(s.h1[half][b][k], Wc1[hj * HH + k], a);
                hs[hj * GSTR + b] = fmaxf(a, 0.0f);
            }
        }
    }
    __syncthreads();
    if (lt < NBH * NC) {
        int b = lt / NC, c = lt - b * NC;
        if (bbase + b < BB) {
            float* hs = s.gates[half][0];
            float o = bc2[c];
#pragma unroll
            for (int j = 0; j < HH; j++)
                o = fmaf(hs[j * GSTR + b], Wc2[c * HH + j], o);
            out[(size_t)(bbase + b) * NC + c] = o;
        }
    }
#undef ARRV
#undef WAIT
#undef GBAR
}

extern "C" void kernel_launch(void* const* d_in, const int* in_sizes, int n_in,
                              void* d_out, int out_size) {
    const float* x    = (const float*)d_in[0];
    const float* Wih0 = (const float*)d_in[1];
    const float* Whh0 = (const float*)d_in[2];
    const float* bih0 = (const float*)d_in[3];
    const float* bhh0 = (const float*)d_in[4];
    const float* Wih1 = (const float*)d_in[5];
    const float* Whh1 = (const float*)d_in[6];
    const float* bih1 = (const float*)d_in[7];
    const float* bhh1 = (const float*)d_in[8];
    const float* Wc1  = (const float*)d_in[9];
    const float* bc1  = (const float*)d_in[10];
    const float* Wc2  = (const float*)d_in[11];
    const float* bc2  = (const float*)d_in[12];
    float* out = (float*)d_out;

    lstm_fused_kernel<<<GRIDN, 256>>>(
        x, Wih0, Whh0, bih0, bhh0, Wih1, Whh1, bih1, bhh1,
        Wc1, bc1, Wc2, bc2, out);
}